// round 12
// baseline (speedup 1.0000x reference)
#include <cuda_runtime.h>
#include <cuda_bf16.h>
#include <cstdint>

#define BATCH 4
#define NN 4096
#define MM 4096
#define KF 67                  // 3 pos + 64 feat
#define KSEG 201               // [s0(67) | s1(67) | s2(67)]
#define ROWB 432               // row stride bytes (216 bf16 cols) -> conflict-free ldmatrix
#define KCHUNK 13              // 13 * 16 = 208 >= 201 (cols 201..215 zero)
#define LOG2E 1.4426950408889634f

#define TILE 128               // A tile rows (and packed tile rows)
#define BTILE 64               // B tile rows per job
#define NT 32
#define NJOBS (BATCH * NT * (MM / BTILE))   // 8192
#define NBLK 296                            // 2 persistent CTAs per SM
#define TILE_B (TILE * ROWB)                // 55296 bytes (full packed tile)
#define HALF_B (BTILE * ROWB)               // 27648 bytes (one B job tile)
#define TILE_CHUNKS (TILE_B / 16)           // 3456
#define HALF_CHUNKS (HALF_B / 16)           // 1728

// smem layout (bytes) per CTA
#define SM_A    0
#define SM_B0   (SM_A + TILE_B)       // 55296
#define SM_B1   (SM_B0 + HALF_B)      // 82944
#define SM_R1   (SM_B1 + HALF_B)      // 110592
#define SM_R20  (SM_R1 + 512)         // 111104
#define SM_R21  (SM_R20 + 256)        // 111360
#define SM_RED  (SM_R21 + 256)        // 111616
#define SM_TOT  (SM_RED + 1024)       // 112640  (x2 CTAs = 225280)

// ---------------- helpers ----------------
__device__ __forceinline__ float ex2f(float x) {
    float y; asm("ex2.approx.ftz.f32 %0, %1;" : "=f"(y) : "f"(x)); return y;
}
__device__ __forceinline__ uint32_t smem_u32(const void* p) {
    uint32_t a;
    asm("{ .reg .u64 t; cvta.to.shared.u64 t, %1; cvt.u32.u64 %0, t; }" : "=r"(a) : "l"(p));
    return a;
}
__device__ __forceinline__ void cp16(uint32_t dst, const void* src) {
    asm volatile("cp.async.cg.shared.global [%0], [%1], 16;" :: "r"(dst), "l"(src) : "memory");
}
__device__ __forceinline__ void cp_commit() {
    asm volatile("cp.async.commit_group;" ::: "memory");
}
__device__ __forceinline__ void cp_wait1() {
    asm volatile("cp.async.wait_group 1;" ::: "memory");
}
__device__ __forceinline__ void ldsm4(uint32_t* r, uint32_t a) {
    asm volatile("ldmatrix.sync.aligned.m8n8.x4.shared.b16 {%0,%1,%2,%3}, [%4];"
                 : "=r"(r[0]), "=r"(r[1]), "=r"(r[2]), "=r"(r[3]) : "r"(a));
}
__device__ __forceinline__ void ldsm2(uint32_t* r, uint32_t a) {
    asm volatile("ldmatrix.sync.aligned.m8n8.x2.shared.b16 {%0,%1}, [%2];"
                 : "=r"(r[0]), "=r"(r[1]) : "r"(a));
}
__device__ __forceinline__ void mma_bf16(float* d, const uint32_t* a, const uint32_t* b) {
    asm volatile(
        "mma.sync.aligned.m16n8k16.row.col.f32.bf16.bf16.f32 "
        "{%0,%1,%2,%3}, {%4,%5,%6,%7}, {%8,%9}, {%0,%1,%2,%3};"
        : "+f"(d[0]), "+f"(d[1]), "+f"(d[2]), "+f"(d[3])
        : "r"(a[0]), "r"(a[1]), "r"(a[2]), "r"(a[3]), "r"(b[0]), "r"(b[1]));
}

// ---------------- global scratch ----------------
__device__ __align__(128) unsigned char g_A2[BATCH * NT * TILE_B];  // ~7 MB
__device__ __align__(128) unsigned char g_B2[BATCH * NT * TILE_B];  // ~7 MB (32 tiles of 128 rows)
__device__ float  g_r1[BATCH * NN];
__device__ float  g_r2[BATCH * MM];
__device__ double g_acc[BATCH];

__global__ void zero_kernel() {
    if (threadIdx.x < BATCH) g_acc[threadIdx.x] = 0.0;
}

// ---------------- pack kernels: warp-per-row, coalesced 432B row stores ----------
// IS_A: segments [hi, lo, hi]; else [hi, hi, lo]   (lo = bf16(x - bf16(x)))
template <bool IS_A>
__global__ void pack_kernel(const float* __restrict__ pos,
                            const float* __restrict__ feat,
                            const float* __restrict__ wgt) {
    int gw   = (blockIdx.x * blockDim.x + threadIdx.x) >> 5;  // row index
    int lane = threadIdx.x & 31;
    if (gw >= BATCH * NN) return;
    int b = gw >> 12, n = gw & 4095;

    const float* p = pos + (size_t)gw * 3;
    const float* f = feat + (size_t)gw * 64;

    unsigned char* base = (IS_A ? g_A2 : g_B2);
    unsigned char* rowp = base + (size_t)(b * NT + (n >> 7)) * TILE_B + (size_t)(n & 127) * ROWB;

    if (lane < 27) {
        uint4 val;
        unsigned short* hp = (unsigned short*)&val;
#pragma unroll
        for (int e = 0; e < 8; e++) {
            int c = lane * 8 + e;
            __nv_bfloat16 v = __float2bfloat16(0.0f);
            if (c < KSEG) {
                int seg = (c >= 2 * KF) ? 2 : (c >= KF ? 1 : 0);
                int i = c - seg * KF;
                float x;
                if (IS_A) x = (i < 3) ? (2.0f * LOG2E) * p[i] : (-0.5f * LOG2E) * f[i - 3];
                else      x = (i < 3) ? 2.0f * p[i] : f[i - 3];
                __nv_bfloat16 h1 = __float2bfloat16(x);
                bool residual = IS_A ? (seg == 1) : (seg == 2);
                v = residual ? __float2bfloat16(x - __bfloat162float(h1)) : h1;
            }
            hp[e] = *(unsigned short*)&v;
        }
        *(uint4*)(rowp + lane * 16) = val;
    } else if (lane == 27) {
        float sq = p[0]*p[0] + p[1]*p[1] + p[2]*p[2];
        float r = -2.0f * LOG2E * sq + __log2f(wgt[gw]);
        if (IS_A) g_r1[gw] = r; else g_r2[gw] = r;
    }
}

// ---------------- main HMMA kernel ----------------
// 296 persistent CTAs (2/SM), 256 threads = 8 warps (2 m-halves x 4 n-quarters).
// A tile 128 rows resident; B job tile 64 rows double-buffered via cp.async.
// Warp tile 64x16: 4 mi x 2 ni x 13 kc MMAs.
__global__ __launch_bounds__(256, 2) void varifold_hmma_kernel() {
    extern __shared__ unsigned char smem[];
    const uint32_t sb = smem_u32(smem);
    float* r1s = (float*)(smem + SM_R1);
    float* red = (float*)(smem + SM_RED);

    const int tid  = threadIdx.x;
    const int lane = tid & 31;
    const int w    = tid >> 5;
    const int wm   = w & 1;        // m-half: rows wm*64..+63
    const int wn   = w >> 1;       // n-quarter: cols wn*16..+15

    // per-thread ldmatrix offsets (relative to tile base)
    const uint32_t a_rel = (uint32_t)(wm * 64 + (lane & 7) + ((lane >> 3) & 1) * 8) * ROWB
                         + ((lane >> 4) & 1) * 16;
    const int l2 = lane & 15;
    const uint32_t b_rel = (uint32_t)(wn * 16 + (l2 & 7)) * ROWB + ((l2 >> 3) & 1) * 16;

    const int jstart = (int)(((long long)blockIdx.x * NJOBS) / NBLK);
    const int jend   = (int)(((long long)(blockIdx.x + 1) * NJOBS) / NBLK);
    if (jstart >= jend) return;

    float bt0 = 0.0f, bt1 = 0.0f, bt2 = 0.0f, bt3 = 0.0f;

    // job j: b = j>>11, bn = j>>6 (b*32+nt), ms = j&63 (64-row B subtile)
    // B slice source: tile (j>>6 of B side? no: b*32 + (ms>>1)), rows (ms&1)*64
    // r2 slice: g_r2 + b*MM + ms*64

    // ---- prologue: load A(jstart), r1, B(jstart), r2 as one group ----
    {
        const int j = jstart;
        const int b = j >> 11, ms = j & 63;
        const int bn = j >> 6;
        const unsigned char* asrc = g_A2 + (size_t)bn * TILE_B;
        const unsigned char* bsrc = g_B2 + (size_t)(b * NT + (ms >> 1)) * TILE_B
                                  + (size_t)(ms & 1) * HALF_B;
        uint32_t bbuf = (j & 1) ? SM_B1 : SM_B0;
        uint32_t rbuf = (j & 1) ? SM_R21 : SM_R20;
        for (int i = tid; i < TILE_CHUNKS; i += 256)
            cp16(sb + SM_A + i * 16, asrc + (size_t)i * 16);
        for (int i = tid; i < HALF_CHUNKS; i += 256)
            cp16(sb + bbuf + i * 16, bsrc + (size_t)i * 16);
        if (tid < 32) cp16(sb + SM_R1 + tid * 16, g_r1 + bn * 128 + tid * 4);
        if (tid < 16) cp16(sb + rbuf + tid * 16, g_r2 + b * MM + ms * 64 + tid * 4);
        cp_commit();
    }

    for (int j = jstart; j < jend; ++j) {
        const int s  = j & 1;
        const int b  = j >> 11;
        const int bn = j >> 6;
        const bool nextSame = (j + 1 < jend) && (((j + 1) >> 6) == bn);

        __syncthreads();   // all warps done with job j-1 (buffer s^1 free)

        if (nextSame) {
            const int j1 = j + 1;
            const int b1 = j1 >> 11, ms1 = j1 & 63;
            const unsigned char* bsrc = g_B2 + (size_t)(b1 * NT + (ms1 >> 1)) * TILE_B
                                      + (size_t)(ms1 & 1) * HALF_B;
            uint32_t bbuf = (j1 & 1) ? SM_B1 : SM_B0;
            uint32_t rbuf = (j1 & 1) ? SM_R21 : SM_R20;
            for (int i = tid; i < HALF_CHUNKS; i += 256)
                cp16(sb + bbuf + i * 16, bsrc + (size_t)i * 16);
            if (tid < 16)
                cp16(sb + rbuf + tid * 16, g_r2 + b1 * MM + ms1 * 64 + tid * 4);
        }
        cp_commit();       // group for j+1 (possibly empty)
        cp_wait1();        // group for j retired
        __syncthreads();   // publish B(j)

        // ---- compute job j ----
        const uint32_t a_base = sb + SM_A + a_rel;
        const uint32_t b_base = sb + (s ? SM_B1 : SM_B0) + b_rel;
        const float* r2s = (const float*)(smem + (s ? SM_R21 : SM_R20));

        float acc[4][2][4];
#pragma unroll
        for (int mi = 0; mi < 4; mi++)
#pragma unroll
            for (int ni = 0; ni < 2; ni++)
#pragma unroll
                for (int q = 0; q < 4; q++) acc[mi][ni][q] = 0.0f;

#pragma unroll 1
        for (int kc = 0; kc < KCHUNK; kc++) {
            uint32_t af[4][4], bf[2][2];
#pragma unroll
            for (int mi = 0; mi < 4; mi++)
                ldsm4(af[mi], a_base + mi * (16 * ROWB) + kc * 32);
#pragma unroll
            for (int ni = 0; ni < 2; ni++)
                ldsm2(bf[ni], b_base + ni * (8 * ROWB) + kc * 32);
#pragma unroll
            for (int mi = 0; mi < 4; mi++)
#pragma unroll
                for (int ni = 0; ni < 2; ni++)
                    mma_bf16(acc[mi][ni], af[mi], bf[ni]);
        }

        // epilogue: d + r1[row] + r2[col] -> exp2; 4 partial sums
        const int r0 = wm * 64 + (lane >> 2);
        const int c0 = wn * 16 + 2 * (lane & 3);
        float t0 = 0.0f, t1 = 0.0f, t2 = 0.0f, t3 = 0.0f;
#pragma unroll
        for (int mi = 0; mi < 4; mi++) {
            float r1a = r1s[r0 + mi * 16];
            float r1b = r1s[r0 + mi * 16 + 8];
#pragma unroll
            for (int ni = 0; ni < 2; ni++) {
                float r2a = r2s[c0 + ni * 8];
                float r2b = r2s[c0 + ni * 8 + 1];
                t0 += ex2f(acc[mi][ni][0] + r1a + r2a);
                t1 += ex2f(acc[mi][ni][1] + r1a + r2b);
                t2 += ex2f(acc[mi][ni][2] + r1b + r2a);
                t3 += ex2f(acc[mi][ni][3] + r1b + r2b);
            }
        }
        float ts = (t0 + t1) + (t2 + t3);
        if      (b == 0) bt0 += ts;
        else if (b == 1) bt1 += ts;
        else if (b == 2) bt2 += ts;
        else             bt3 += ts;

        // ---- A changes at j+1: flush pipeline and reload A + B(j+1) ----
        if (!nextSame && j + 1 < jend) {
            __syncthreads();   // all warps done reading A
            const int j1 = j + 1;
            const int b1 = j1 >> 11, ms1 = j1 & 63;
            const int bn1 = j1 >> 6;
            const unsigned char* asrc = g_A2 + (size_t)bn1 * TILE_B;
            const unsigned char* bsrc = g_B2 + (size_t)(b1 * NT + (ms1 >> 1)) * TILE_B
                                      + (size_t)(ms1 & 1) * HALF_B;
            uint32_t bbuf = (j1 & 1) ? SM_B1 : SM_B0;
            uint32_t rbuf = (j1 & 1) ? SM_R21 : SM_R20;
            for (int i = tid; i < TILE_CHUNKS; i += 256)
                cp16(sb + SM_A + i * 16, asrc + (size_t)i * 16);
            for (int i = tid; i < HALF_CHUNKS; i += 256)
                cp16(sb + bbuf + i * 16, bsrc + (size_t)i * 16);
            if (tid < 32) cp16(sb + SM_R1 + tid * 16, g_r1 + bn1 * 128 + tid * 4);
            if (tid < 16) cp16(sb + rbuf + tid * 16, g_r2 + b1 * MM + ms1 * 64 + tid * 4);
            cp_commit();
        }
    }

    // per-batch block reduction, one double atomic per touched batch
#pragma unroll
    for (int bb = 0; bb < BATCH; bb++) {
        float v = (bb == 0) ? bt0 : (bb == 1) ? bt1 : (bb == 2) ? bt2 : bt3;
        __syncthreads();
        red[tid] = v;
        __syncthreads();
#pragma unroll
        for (int st = 128; st > 0; st >>= 1) {
            if (tid < st) red[tid] += red[tid + st];
            __syncthreads();
        }
        if (tid == 0 && red[0] != 0.0f) atomicAdd(&g_acc[bb], (double)red[0]);
    }
}

__global__ void finalize_kernel(float* __restrict__ out) {
    if (threadIdx.x < BATCH) out[threadIdx.x] = (float)g_acc[threadIdx.x];
}

extern "C" void kernel_launch(void* const* d_in, const int* in_sizes, int n_in,
                              void* d_out, int out_size) {
    const float* pos1  = (const float*)d_in[0];
    const float* feat1 = (const float*)d_in[1];
    const float* w1    = (const float*)d_in[2];
    const float* pos2  = (const float*)d_in[3];
    const float* feat2 = (const float*)d_in[4];
    const float* w2    = (const float*)d_in[5];
    float* out = (float*)d_out;

    cudaFuncSetAttribute(varifold_hmma_kernel,
                         cudaFuncAttributeMaxDynamicSharedMemorySize, SM_TOT);

    zero_kernel<<<1, 32>>>();
    // 8 rows per 256-thread block
    pack_kernel<true><<<(BATCH * NN) / 8, 256>>>(pos1, feat1, w1);
    pack_kernel<false><<<(BATCH * MM) / 8, 256>>>(pos2, feat2, w2);

    varifold_hmma_kernel<<<NBLK, 256, SM_TOT>>>();

    finalize_kernel<<<1, 32>>>(out);
}

// round 13
// speedup vs baseline: 1.1358x; 1.1358x over previous
#include <cuda_runtime.h>
#include <cuda_bf16.h>
#include <cstdint>

#define BATCH 4
#define NN 4096
#define MM 4096
#define KF 67                  // 3 pos + 64 feat
#define KSEG 201               // [s0(67) | s1(67) | s2(67)]
#define ROWB 432               // row stride bytes (216 bf16 cols) -> conflict-free ldmatrix
#define KCHUNK 13              // 13 * 16 = 208 >= 201 (cols 201..215 zero)
#define LOG2E 1.4426950408889634f

#define TILE 128
#define NT 32
#define MT 32
#define NJOBS (BATCH * NT * MT)      // 4096
#define NBLK 296                     // 2 persistent CTAs per SM
#define TILE_B (TILE * ROWB)         // 55296 bytes per packed tile
#define TILE_CHUNKS (TILE_B / 16)    // 3456

// smem layout (bytes)
#define SM_AS   0
#define SM_BS   (SM_AS + TILE_B)      // 55296
#define SM_R1   (SM_BS + TILE_B)      // 110592
#define SM_R2   (SM_R1 + 512)         // 111104
#define SM_RED  (SM_R2 + 512)         // 111616
#define SM_TOT  (SM_RED + 1024)       // 112640  (x2 CTAs = 225280 <= smem/SM)

// ---------------- helpers ----------------
__device__ __forceinline__ float ex2f(float x) {
    float y; asm("ex2.approx.ftz.f32 %0, %1;" : "=f"(y) : "f"(x)); return y;
}
__device__ __forceinline__ uint32_t smem_u32(const void* p) {
    uint32_t a;
    asm("{ .reg .u64 t; cvta.to.shared.u64 t, %1; cvt.u32.u64 %0, t; }" : "=r"(a) : "l"(p));
    return a;
}
__device__ __forceinline__ void cp16(uint32_t dst, const void* src) {
    asm volatile("cp.async.cg.shared.global [%0], [%1], 16;" :: "r"(dst), "l"(src) : "memory");
}
__device__ __forceinline__ void cp_commit_wait() {
    asm volatile("cp.async.commit_group;" ::: "memory");
    asm volatile("cp.async.wait_group 0;" ::: "memory");
}
__device__ __forceinline__ void ldsm4(uint32_t* r, uint32_t a) {
    asm volatile("ldmatrix.sync.aligned.m8n8.x4.shared.b16 {%0,%1,%2,%3}, [%4];"
                 : "=r"(r[0]), "=r"(r[1]), "=r"(r[2]), "=r"(r[3]) : "r"(a));
}
__device__ __forceinline__ void ldsm2(uint32_t* r, uint32_t a) {
    asm volatile("ldmatrix.sync.aligned.m8n8.x2.shared.b16 {%0,%1}, [%2];"
                 : "=r"(r[0]), "=r"(r[1]) : "r"(a));
}
__device__ __forceinline__ void mma_bf16(float* d, const uint32_t* a, const uint32_t* b) {
    asm volatile(
        "mma.sync.aligned.m16n8k16.row.col.f32.bf16.bf16.f32 "
        "{%0,%1,%2,%3}, {%4,%5,%6,%7}, {%8,%9}, {%0,%1,%2,%3};"
        : "+f"(d[0]), "+f"(d[1]), "+f"(d[2]), "+f"(d[3])
        : "r"(a[0]), "r"(a[1]), "r"(a[2]), "r"(a[3]), "r"(b[0]), "r"(b[1]));
}

// ---------------- global scratch ----------------
__device__ __align__(128) unsigned char g_A2[BATCH * NT * TILE_B];  // ~7 MB
__device__ __align__(128) unsigned char g_B2[BATCH * MT * TILE_B];  // ~7 MB
__device__ float  g_r1[BATCH * NN];
__device__ float  g_r2[BATCH * MM];
__device__ double g_acc[BATCH];

__global__ void zero_kernel() {
    if (threadIdx.x < BATCH) g_acc[threadIdx.x] = 0.0;
}

// ---------------- pack kernels: warp-per-row, coalesced 432B row stores ----------
// IS_A: segments [hi, lo, hi]; else [hi, hi, lo]   (lo = bf16(x - bf16(x)))
template <bool IS_A>
__global__ void pack_kernel(const float* __restrict__ pos,
                            const float* __restrict__ feat,
                            const float* __restrict__ wgt) {
    int gw   = (blockIdx.x * blockDim.x + threadIdx.x) >> 5;  // row index
    int lane = threadIdx.x & 31;
    if (gw >= BATCH * NN) return;
    int b = gw >> 12, n = gw & 4095;

    const float* p = pos + (size_t)gw * 3;
    const float* f = feat + (size_t)gw * 64;

    unsigned char* base = (IS_A ? g_A2 : g_B2);
    unsigned char* rowp = base + (size_t)(b * NT + (n >> 7)) * TILE_B + (size_t)(n & 127) * ROWB;

    if (lane < 27) {
        uint4 val;
        unsigned short* hp = (unsigned short*)&val;
#pragma unroll
        for (int e = 0; e < 8; e++) {
            int c = lane * 8 + e;
            __nv_bfloat16 v = __float2bfloat16(0.0f);
            if (c < KSEG) {
                int seg = (c >= 2 * KF) ? 2 : (c >= KF ? 1 : 0);
                int i = c - seg * KF;
                float x;
                if (IS_A) x = (i < 3) ? (2.0f * LOG2E) * p[i] : (-0.5f * LOG2E) * f[i - 3];
                else      x = (i < 3) ? 2.0f * p[i] : f[i - 3];
                __nv_bfloat16 h1 = __float2bfloat16(x);
                bool residual = IS_A ? (seg == 1) : (seg == 2);
                v = residual ? __float2bfloat16(x - __bfloat162float(h1)) : h1;
            }
            hp[e] = *(unsigned short*)&v;
        }
        *(uint4*)(rowp + lane * 16) = val;
    } else if (lane == 27) {
        float sq = p[0]*p[0] + p[1]*p[1] + p[2]*p[2];
        float r = -2.0f * LOG2E * sq + __log2f(wgt[gw]);
        if (IS_A) g_r1[gw] = r; else g_r2[gw] = r;
    }
}

// ---------------- main HMMA kernel ----------------
// 296 persistent CTAs (2/SM), 256 threads = 8 warps (2 m-halves x 4 n-quarters).
// Warp tile 64x32; register-pipelined kc loop (A frags prefetched one kc ahead).
__global__ __launch_bounds__(256, 2) void varifold_hmma_kernel() {
    extern __shared__ unsigned char smem[];
    const uint32_t sb = smem_u32(smem);
    float* r1s = (float*)(smem + SM_R1);
    float* r2s = (float*)(smem + SM_R2);
    float* red = (float*)(smem + SM_RED);

    const int tid  = threadIdx.x;
    const int lane = tid & 31;
    const int w    = tid >> 5;
    const int wm   = w & 1;        // m-half: rows wm*64..+63
    const int wn   = w >> 1;       // n-quarter: cols wn*32..+31

    // per-thread ldmatrix base offsets
    const uint32_t a_base = sb + SM_AS
        + (uint32_t)(wm * 64 + (lane & 7) + ((lane >> 3) & 1) * 8) * ROWB
        + ((lane >> 4) & 1) * 16;
    const int l2 = lane & 15;
    const uint32_t b_base = sb + SM_BS
        + (uint32_t)(wn * 32 + (l2 & 7)) * ROWB
        + ((l2 >> 3) & 1) * 16;

    const int jstart = (int)(((long long)blockIdx.x * NJOBS) / NBLK);
    const int jend   = (int)(((long long)(blockIdx.x + 1) * NJOBS) / NBLK);

    int cur_bn = -1;
    float bt0 = 0.0f, bt1 = 0.0f, bt2 = 0.0f, bt3 = 0.0f;

    for (int job = jstart; job < jend; ++job) {
        const int b  = job >> 10;
        const int nt = (job >> 5) & 31;
        const int mt = job & 31;
        const int bn = job >> 5;

        __syncthreads();           // previous tile's smem consumers done
        if (bn != cur_bn) {
            const unsigned char* src = g_A2 + (size_t)bn * TILE_B;
            for (int i = tid; i < TILE_CHUNKS; i += 256)
                cp16(sb + SM_AS + i * 16, src + (size_t)i * 16);
            if (tid < 32) cp16(sb + SM_R1 + tid * 16, g_r1 + bn * 128 + tid * 4);
            cur_bn = bn;
        }
        {
            const unsigned char* src = g_B2 + (size_t)(b * MT + mt) * TILE_B;
            for (int i = tid; i < TILE_CHUNKS; i += 256)
                cp16(sb + SM_BS + i * 16, src + (size_t)i * 16);
            if (tid < 32) cp16(sb + SM_R2 + tid * 16, g_r2 + (b * MT + mt) * 128 + tid * 4);
        }
        cp_commit_wait();
        __syncthreads();

        float acc[4][4][4];
#pragma unroll
        for (int mi = 0; mi < 4; mi++)
#pragma unroll
            for (int ni = 0; ni < 4; ni++)
#pragma unroll
                for (int q = 0; q < 4; q++) acc[mi][ni][q] = 0.0f;

        // ---- register-pipelined mainloop: A frags double-buffered across kc ----
        uint32_t afA[4][4], afB[4][4], bf[4][2];
#pragma unroll
        for (int mi = 0; mi < 4; mi++)
            ldsm4(afA[mi], a_base + mi * (16 * ROWB));          // kc = 0

#pragma unroll
        for (int kc = 0; kc < KCHUNK; kc++) {
            uint32_t (*cur)[4] = (kc & 1) ? afB : afA;
            uint32_t (*nxt)[4] = (kc & 1) ? afA : afB;
            // B frags for this kc
#pragma unroll
            for (int ni = 0; ni < 4; ni++)
                ldsm2(bf[ni], b_base + ni * (8 * ROWB) + kc * 32);
            // prefetch next kc's A frags while MMAs below run
            if (kc + 1 < KCHUNK) {
#pragma unroll
                for (int mi = 0; mi < 4; mi++)
                    ldsm4(nxt[mi], a_base + mi * (16 * ROWB) + (kc + 1) * 32);
            }
#pragma unroll
            for (int mi = 0; mi < 4; mi++)
#pragma unroll
                for (int ni = 0; ni < 4; ni++)
                    mma_bf16(acc[mi][ni], cur[mi], bf[ni]);
        }

        // epilogue: d + r1[row] + r2[col] -> exp2; 4 partial sums
        const int r0 = wm * 64 + (lane >> 2);
        const int c0 = wn * 32 + 2 * (lane & 3);
        float t0 = 0.0f, t1 = 0.0f, t2 = 0.0f, t3 = 0.0f;
#pragma unroll
        for (int mi = 0; mi < 4; mi++) {
            float r1a = r1s[r0 + mi * 16];
            float r1b = r1s[r0 + mi * 16 + 8];
#pragma unroll
            for (int ni = 0; ni < 4; ni++) {
                float r2a = r2s[c0 + ni * 8];
                float r2b = r2s[c0 + ni * 8 + 1];
                t0 += ex2f(acc[mi][ni][0] + r1a + r2a);
                t1 += ex2f(acc[mi][ni][1] + r1a + r2b);
                t2 += ex2f(acc[mi][ni][2] + r1b + r2a);
                t3 += ex2f(acc[mi][ni][3] + r1b + r2b);
            }
        }
        float ts = (t0 + t1) + (t2 + t3);
        if      (b == 0) bt0 += ts;
        else if (b == 1) bt1 += ts;
        else if (b == 2) bt2 += ts;
        else             bt3 += ts;
    }

    // per-batch block reduction, one double atomic per touched batch
#pragma unroll
    for (int bb = 0; bb < BATCH; bb++) {
        float v = (bb == 0) ? bt0 : (bb == 1) ? bt1 : (bb == 2) ? bt2 : bt3;
        __syncthreads();
        red[tid] = v;
        __syncthreads();
#pragma unroll
        for (int s = 128; s > 0; s >>= 1) {
            if (tid < s) red[tid] += red[tid + s];
            __syncthreads();
        }
        if (tid == 0 && red[0] != 0.0f) atomicAdd(&g_acc[bb], (double)red[0]);
    }
}

__global__ void finalize_kernel(float* __restrict__ out) {
    if (threadIdx.x < BATCH) out[threadIdx.x] = (float)g_acc[threadIdx.x];
}

extern "C" void kernel_launch(void* const* d_in, const int* in_sizes, int n_in,
                              void* d_out, int out_size) {
    const float* pos1  = (const float*)d_in[0];
    const float* feat1 = (const float*)d_in[1];
    const float* w1    = (const float*)d_in[2];
    const float* pos2  = (const float*)d_in[3];
    const float* feat2 = (const float*)d_in[4];
    const float* w2    = (const float*)d_in[5];
    float* out = (float*)d_out;

    cudaFuncSetAttribute(varifold_hmma_kernel,
                         cudaFuncAttributeMaxDynamicSharedMemorySize, SM_TOT);

    zero_kernel<<<1, 32>>>();
    // 8 rows per 256-thread block
    pack_kernel<true><<<(BATCH * NN) / 8, 256>>>(pos1, feat1, w1);
    pack_kernel<false><<<(BATCH * MM) / 8, 256>>>(pos2, feat2, w2);

    varifold_hmma_kernel<<<NBLK, 256, SM_TOT>>>();

    finalize_kernel<<<1, 32>>>(out);
}

// round 15
// speedup vs baseline: 1.1717x; 1.0316x over previous
#include <cuda_runtime.h>
#include <cuda_bf16.h>
#include <cstdint>

#define BATCH 4
#define NN 4096
#define MM 4096
#define KF 67                  // 3 pos + 64 feat
#define KSEG 201               // [s0(67) | s1(67) | s2(67)]
#define ROWB 432               // row stride bytes (216 bf16 cols) -> conflict-free ldmatrix
#define KCHUNK 13              // 13 * 16 = 208 >= 201 (cols 201..215 zero)
#define LOG2E 1.4426950408889634f

#define TILE 128
#define NT 32
#define MT 32
#define NJOBS (BATCH * NT * MT)      // 4096
#define NBLK 296                     // 2 persistent CTAs per SM
#define TILE_B (TILE * ROWB)         // 55296 bytes per packed tile
#define TILE_CHUNKS (TILE_B / 16)    // 3456

// smem layout (bytes)
#define SM_AS   0
#define SM_BS   (SM_AS + TILE_B)      // 55296
#define SM_R1   (SM_BS + TILE_B)      // 110592
#define SM_R2A  (SM_R1 + 512)         // 111104
#define SM_R2B  (SM_R2A + 512)        // 111616
#define SM_RED  (SM_R2B + 512)        // 112128
#define SM_TOT  (SM_RED + 1024)       // 113152  (x2 CTAs = 226304 <= smem/SM)

// ---------------- helpers ----------------
__device__ __forceinline__ float ex2f(float x) {
    float y; asm("ex2.approx.ftz.f32 %0, %1;" : "=f"(y) : "f"(x)); return y;
}
__device__ __forceinline__ uint32_t smem_u32(const void* p) {
    uint32_t a;
    asm("{ .reg .u64 t; cvta.to.shared.u64 t, %1; cvt.u32.u64 %0, t; }" : "=r"(a) : "l"(p));
    return a;
}
__device__ __forceinline__ void cp16(uint32_t dst, const void* src) {
    asm volatile("cp.async.cg.shared.global [%0], [%1], 16;" :: "r"(dst), "l"(src) : "memory");
}
__device__ __forceinline__ void cp_commit() {
    asm volatile("cp.async.commit_group;" ::: "memory");
}
__device__ __forceinline__ void cp_wait0() {
    asm volatile("cp.async.wait_group 0;" ::: "memory");
}
__device__ __forceinline__ void ldsm4(uint32_t* r, uint32_t a) {
    asm volatile("ldmatrix.sync.aligned.m8n8.x4.shared.b16 {%0,%1,%2,%3}, [%4];"
                 : "=r"(r[0]), "=r"(r[1]), "=r"(r[2]), "=r"(r[3]) : "r"(a));
}
__device__ __forceinline__ void ldsm2(uint32_t* r, uint32_t a) {
    asm volatile("ldmatrix.sync.aligned.m8n8.x2.shared.b16 {%0,%1}, [%2];"
                 : "=r"(r[0]), "=r"(r[1]) : "r"(a));
}
__device__ __forceinline__ void mma_bf16(float* d, const uint32_t* a, const uint32_t* b) {
    asm volatile(
        "mma.sync.aligned.m16n8k16.row.col.f32.bf16.bf16.f32 "
        "{%0,%1,%2,%3}, {%4,%5,%6,%7}, {%8,%9}, {%0,%1,%2,%3};"
        : "+f"(d[0]), "+f"(d[1]), "+f"(d[2]), "+f"(d[3])
        : "r"(a[0]), "r"(a[1]), "r"(a[2]), "r"(a[3]), "r"(b[0]), "r"(b[1]));
}

// ---------------- global scratch ----------------
__device__ __align__(128) unsigned char g_A2[BATCH * NT * TILE_B];  // ~7 MB
__device__ __align__(128) unsigned char g_B2[BATCH * MT * TILE_B];  // ~7 MB
__device__ float  g_r1[BATCH * NN];
__device__ float  g_r2[BATCH * MM];
__device__ double g_acc[BATCH];

__global__ void zero_kernel() {
    if (threadIdx.x < BATCH) g_acc[threadIdx.x] = 0.0;
}

// ---------------- pack kernels: warp-per-row, coalesced 432B row stores ----------
// IS_A: segments [hi, lo, hi]; else [hi, hi, lo]   (lo = bf16(x - bf16(x)))
template <bool IS_A>
__global__ void pack_kernel(const float* __restrict__ pos,
                            const float* __restrict__ feat,
                            const float* __restrict__ wgt) {
    int gw   = (blockIdx.x * blockDim.x + threadIdx.x) >> 5;  // row index
    int lane = threadIdx.x & 31;
    if (gw >= BATCH * NN) return;
    int b = gw >> 12, n = gw & 4095;

    const float* p = pos + (size_t)gw * 3;
    const float* f = feat + (size_t)gw * 64;

    unsigned char* base = (IS_A ? g_A2 : g_B2);
    unsigned char* rowp = base + (size_t)(b * NT + (n >> 7)) * TILE_B + (size_t)(n & 127) * ROWB;

    if (lane < 27) {
        uint4 val;
        unsigned short* hp = (unsigned short*)&val;
#pragma unroll
        for (int e = 0; e < 8; e++) {
            int c = lane * 8 + e;
            __nv_bfloat16 v = __float2bfloat16(0.0f);
            if (c < KSEG) {
                int seg = (c >= 2 * KF) ? 2 : (c >= KF ? 1 : 0);
                int i = c - seg * KF;
                float x;
                if (IS_A) x = (i < 3) ? (2.0f * LOG2E) * p[i] : (-0.5f * LOG2E) * f[i - 3];
                else      x = (i < 3) ? 2.0f * p[i] : f[i - 3];
                __nv_bfloat16 h1 = __float2bfloat16(x);
                bool residual = IS_A ? (seg == 1) : (seg == 2);
                v = residual ? __float2bfloat16(x - __bfloat162float(h1)) : h1;
            }
            hp[e] = *(unsigned short*)&v;
        }
        *(uint4*)(rowp + lane * 16) = val;
    } else if (lane == 27) {
        float sq = p[0]*p[0] + p[1]*p[1] + p[2]*p[2];
        float r = -2.0f * LOG2E * sq + __log2f(wgt[gw]);
        if (IS_A) g_r1[gw] = r; else g_r2[gw] = r;
    }
}

// ---------------- main HMMA kernel ----------------
// 296 persistent CTAs (2/SM), 256 threads = 8 warps (2 m-halves x 4 n-quarters).
// Warp tile 64x32; register-pipelined kc loop; B(j+1) prefetched into the SAME
// Bs buffer during epilogue(j) (Bs has no readers after the mainloop).
__global__ __launch_bounds__(256, 2) void varifold_hmma_kernel() {
    extern __shared__ unsigned char smem[];
    const uint32_t sb = smem_u32(smem);
    float* r1s = (float*)(smem + SM_R1);
    float* red = (float*)(smem + SM_RED);

    const int tid  = threadIdx.x;
    const int lane = tid & 31;
    const int w    = tid >> 5;
    const int wm   = w & 1;        // m-half: rows wm*64..+63
    const int wn   = w >> 1;       // n-quarter: cols wn*32..+31

    // per-thread ldmatrix base offsets
    const uint32_t a_base = sb + SM_AS
        + (uint32_t)(wm * 64 + (lane & 7) + ((lane >> 3) & 1) * 8) * ROWB
        + ((lane >> 4) & 1) * 16;
    const int l2 = lane & 15;
    const uint32_t b_base = sb + SM_BS
        + (uint32_t)(wn * 32 + (l2 & 7)) * ROWB
        + ((l2 >> 3) & 1) * 16;

    const int jstart = (int)(((long long)blockIdx.x * NJOBS) / NBLK);
    const int jend   = (int)(((long long)(blockIdx.x + 1) * NJOBS) / NBLK);
    if (jstart >= jend) return;

    float bt0 = 0.0f, bt1 = 0.0f, bt2 = 0.0f, bt3 = 0.0f;

    // ---- prologue: load A(jstart), r1, B(jstart), r2 ----
    {
        const int j = jstart;
        const int bn = j >> 5;
        const int bm = j >> 10 == 0 ? 0 : 0; (void)bm;
        const int bmi = ((j >> 10) << 5) | (j & 31);
        const unsigned char* asrc = g_A2 + (size_t)bn * TILE_B;
        const unsigned char* bsrc = g_B2 + (size_t)bmi * TILE_B;
        uint32_t rbuf = (j & 1) ? SM_R2B : SM_R2A;
        for (int i = tid; i < TILE_CHUNKS; i += 256) {
            cp16(sb + SM_AS + i * 16, asrc + (size_t)i * 16);
            cp16(sb + SM_BS + i * 16, bsrc + (size_t)i * 16);
        }
        if (tid < 32) {
            cp16(sb + SM_R1 + tid * 16, g_r1 + bn * 128 + tid * 4);
            cp16(sb + rbuf + tid * 16, g_r2 + bmi * 128 + tid * 4);
        }
        cp_commit();
        cp_wait0();
        __syncthreads();
    }

    for (int job = jstart; job < jend; ++job) {
        const int b  = job >> 10;
        const int bn = job >> 5;

        float acc[4][4][4];
#pragma unroll
        for (int mi = 0; mi < 4; mi++)
#pragma unroll
            for (int ni = 0; ni < 4; ni++)
#pragma unroll
                for (int q = 0; q < 4; q++) acc[mi][ni][q] = 0.0f;

        // ---- register-pipelined mainloop: A frags double-buffered across kc ----
        uint32_t afA[4][4], afB[4][4], bf[4][2];
#pragma unroll
        for (int mi = 0; mi < 4; mi++)
            ldsm4(afA[mi], a_base + mi * (16 * ROWB));          // kc = 0

#pragma unroll
        for (int kc = 0; kc < KCHUNK; kc++) {
            uint32_t (*cur)[4] = (kc & 1) ? afB : afA;
            uint32_t (*nxt)[4] = (kc & 1) ? afA : afB;
#pragma unroll
            for (int ni = 0; ni < 4; ni++)
                ldsm2(bf[ni], b_base + ni * (8 * ROWB) + kc * 32);
            if (kc + 1 < KCHUNK) {
#pragma unroll
                for (int mi = 0; mi < 4; mi++)
                    ldsm4(nxt[mi], a_base + mi * (16 * ROWB) + (kc + 1) * 32);
            }
#pragma unroll
            for (int mi = 0; mi < 4; mi++)
#pragma unroll
                for (int ni = 0; ni < 4; ni++)
                    mma_bf16(acc[mi][ni], cur[mi], bf[ni]);
        }

        // pull r1 values into registers (epilogue must not read r1s after the
        // prefetch below possibly overwrites it on an A-tile change)
        const int r0 = wm * 64 + (lane >> 2);
        float r1v[8];
#pragma unroll
        for (int mi = 0; mi < 4; mi++) {
            r1v[2 * mi]     = r1s[r0 + mi * 16];
            r1v[2 * mi + 1] = r1s[r0 + mi * 16 + 8];
        }

        __syncthreads();   // all warps done reading As/Bs (mainloop complete)

        // ---- prefetch job+1 tiles into the same buffers (rides under epilogue) ----
        const bool haveNext = (job + 1 < jend);
        if (haveNext) {
            const int j1 = job + 1;
            const int bn1 = j1 >> 5;
            const int bmi1 = ((j1 >> 10) << 5) | (j1 & 31);
            uint32_t rbuf = (j1 & 1) ? SM_R2B : SM_R2A;
            if (bn1 != bn) {
                const unsigned char* asrc = g_A2 + (size_t)bn1 * TILE_B;
                for (int i = tid; i < TILE_CHUNKS; i += 256)
                    cp16(sb + SM_AS + i * 16, asrc + (size_t)i * 16);
                if (tid < 32) cp16(sb + SM_R1 + tid * 16, g_r1 + bn1 * 128 + tid * 4);
            }
            const unsigned char* bsrc = g_B2 + (size_t)bmi1 * TILE_B;
            for (int i = tid; i < TILE_CHUNKS; i += 256)
                cp16(sb + SM_BS + i * 16, bsrc + (size_t)i * 16);
            if (tid < 32) cp16(sb + rbuf + tid * 16, g_r2 + bmi1 * 128 + tid * 4);
            cp_commit();
        }

        // ---- epilogue: d + r1[row] + r2[col] -> exp2; 4 partial sums ----
        const float* r2s = (const float*)(smem + ((job & 1) ? SM_R2B : SM_R2A));
        const int c0 = wn * 32 + 2 * (lane & 3);
        float t0 = 0.0f, t1 = 0.0f, t2 = 0.0f, t3 = 0.0f;
#pragma unroll
        for (int mi = 0; mi < 4; mi++) {
            float r1a = r1v[2 * mi];
            float r1b = r1v[2 * mi + 1];
#pragma unroll
            for (int ni = 0; ni < 4; ni++) {
                float r2a = r2s[c0 + ni * 8];
                float r2b = r2s[c0 + ni * 8 + 1];
                t0 += ex2f(acc[mi][ni][0] + r1a + r2a);
                t1 += ex2f(acc[mi][ni][1] + r1a + r2b);
                t2 += ex2f(acc[mi][ni][2] + r1b + r2a);
                t3 += ex2f(acc[mi][ni][3] + r1b + r2b);
            }
        }
        float ts = (t0 + t1) + (t2 + t3);
        if      (b == 0) bt0 += ts;
        else if (b == 1) bt1 += ts;
        else if (b == 2) bt2 += ts;
        else             bt3 += ts;

        if (haveNext) {
            cp_wait0();
            __syncthreads();   // publish tiles for job+1
        }
    }

    // per-batch block reduction, one double atomic per touched batch
#pragma unroll
    for (int bb = 0; bb < BATCH; bb++) {
        float v = (bb == 0) ? bt0 : (bb == 1) ? bt1 : (bb == 2) ? bt2 : bt3;
        __syncthreads();
        red[tid] = v;
        __syncthreads();
#pragma unroll
        for (int s = 128; s > 0; s >>= 1) {
            if (tid < s) red[tid] += red[tid + s];
            __syncthreads();
        }
        if (tid == 0 && red[0] != 0.0f) atomicAdd(&g_acc[bb], (double)red[0]);
    }
}

__global__ void finalize_kernel(float* __restrict__ out) {
    if (threadIdx.x < BATCH) out[threadIdx.x] = (float)g_acc[threadIdx.x];
}

extern "C" void kernel_launch(void* const* d_in, const int* in_sizes, int n_in,
                              void* d_out, int out_size) {
    const float* pos1  = (const float*)d_in[0];
    const float* feat1 = (const float*)d_in[1];
    const float* w1    = (const float*)d_in[2];
    const float* pos2  = (const float*)d_in[3];
    const float* feat2 = (const float*)d_in[4];
    const float* w2    = (const float*)d_in[5];
    float* out = (float*)d_out;

    cudaFuncSetAttribute(varifold_hmma_kernel,
                         cudaFuncAttributeMaxDynamicSharedMemorySize, SM_TOT);

    zero_kernel<<<1, 32>>>();
    // 8 rows per 256-thread block
    pack_kernel<true><<<(BATCH * NN) / 8, 256>>>(pos1, feat1, w1);
    pack_kernel<false><<<(BATCH * MM) / 8, 256>>>(pos2, feat2, w2);

    varifold_hmma_kernel<<<NBLK, 256, SM_TOT>>>();

    finalize_kernel<<<1, 32>>>(out);
}